// round 6
// baseline (speedup 1.0000x reference)
#include <cuda_runtime.h>
#include <math.h>
#include <stdint.h>

#define BB 4
#define TT 1024
#define DD 1024
#define HH 16
#define DKV 64
#define FFD 4096

// ---------------- scratch (device globals; no allocation allowed) ----------------
__device__ float g_Wt0[DD * DD];
__device__ float g_Wt1[DD * DD];
__device__ float g_Wt2[DD * DD];
__device__ float g_WoT[DD * DD];
__device__ float g_Q  [BB * TT * DD];
__device__ float g_K  [BB * TT * DD];
__device__ float g_V  [BB * TT * DD];
__device__ float g_Vt [BB * HH * DKV * TT];
__device__ float g_S  [(size_t)BB * HH * TT * TT];   // 256 MB
__device__ float g_dinv[BB * HH * TT];
__device__ float g_P  [BB * TT * DD];
__device__ float g_M  [BB * TT * DD];
__device__ float g_o1 [BB * TT * DD];
__device__ float g_o2 [BB * TT * DD];
__device__ float g_hid[(size_t)BB * TT * FFD];       // 64 MB
__device__ float g_ff [BB * TT * DD];

// ---------------- helpers ----------------
// pack bf16(trunc) of two floats into one u32: low half = a, high half = b
__device__ __forceinline__ uint32_t pack_bf16(float a, float b) {
    uint32_t d;
    asm("prmt.b32 %0, %1, %2, 0x7632;" : "=r"(d)
        : "r"(__float_as_uint(a)), "r"(__float_as_uint(b)));
    return d;
}
// exact residual after bf16 truncation
__device__ __forceinline__ float resid(float v) {
    return v - __uint_as_float(__float_as_uint(v) & 0xffff0000u);
}
__device__ __forceinline__ void mma_bf16(float* c, const uint32_t* a, const uint32_t* b) {
    asm volatile(
        "mma.sync.aligned.m16n8k16.row.col.f32.bf16.bf16.f32 "
        "{%0,%1,%2,%3}, {%4,%5,%6,%7}, {%8,%9}, {%0,%1,%2,%3};"
        : "+f"(c[0]), "+f"(c[1]), "+f"(c[2]), "+f"(c[3])
        : "r"(a[0]), "r"(a[1]), "r"(a[2]), "r"(a[3]), "r"(b[0]), "r"(b[1]));
}

// ---------------- bf16x3 mma GEMM: C[M,N] = alpha * A[M,K] @ B[N,K]^T -------------
// A K-major (lda), B K-major (ldb). 3-term bf16 split (hi*hi + hi*lo + lo*hi).
// Pre-split at staging: smem holds, per (row, k-quad), a 16B group
//   [hi(k0,k1), hi(k2,k3), lo(k0,k1), lo(k2,k3)]   (2B hi + 2B lo per element)
// so the inner loop is pure LDS.128 + HMMA (zero pack/residual ALU).
// BM=128, BN=64, BK=32 (8 quads/row), 2 smem stages, LDG register prefetch,
// persistent CTAs over all tiles. One __syncthreads per chunk.
template<bool BIAS_, bool RELU_, bool EXP_>
__global__ __launch_bounds__(256, 2)
void mma_gemm(const float* __restrict__ A, const float* __restrict__ B,
              const float* __restrict__ bias, float* __restrict__ C,
              int K, int lda, int ldb, int ldc,
              long sA1, long sA2, long sB1, long sB2, long sC1, long sC2,
              int zdiv, float alpha, int gx, int gy, int ntiles)
{
    constexpr int BM = 128, BN = 64, BK = 32;
    constexpr int NT = 4;              // n-tiles per warp (warp tile 32x32)
    constexpr int MT = 2;
    constexpr int RSW = 48;            // words per smem row (8 quads=32w data +16w pad)
    constexpr int STGW = (BM + BN) * RSW;   // 9216 words per stage
    constexpr int NGRP = (BM + BN) * 8;     // 16B groups per stage = 1536 -> 6/thread

    extern __shared__ float sm[];

    const int tid  = threadIdx.x;
    const int lane = tid & 31;
    const int wid  = tid >> 5;
    const int wm   = wid >> 1;         // 0..3
    const int wn   = wid & 1;          // 0..1
    const int g    = lane >> 2;
    const int tg   = lane & 3;

    const int ar = wm * 32 + g;
    const int br = wn * 32 + g;

    // per-thread staging assignment (fixed): group idx j*256+tid -> (row, quad)
    int rows_[6], qs_[6];
    uint32_t soff[6];                  // smem word offset within stage
    #pragma unroll
    for (int j = 0; j < 6; j++) {
        int idx = j * 256 + tid;
        rows_[j] = idx >> 3;
        qs_[j]   = idx & 7;
        soff[j]  = (uint32_t)(rows_[j] * RSW + qs_[j] * 4);
    }

    for (int tile = blockIdx.x; tile < ntiles; tile += gridDim.x) {
        const int z   = tile / (gx * gy);
        const int rem = tile % (gx * gy);
        const int row0 = (rem / gx) * BM;
        const int col0 = (rem % gx) * BN;
        const int z1 = z / zdiv, z2 = z % zdiv;
        const float* At = A + z1 * sA1 + z2 * sA2;
        const float* Bt = B + z1 * sB1 + z2 * sB2;
        float*       Ct = C + z1 * sC1 + z2 * sC2;

        const float* gptr[6];
        #pragma unroll
        for (int j = 0; j < 6; j++) {
            int r = rows_[j];
            gptr[j] = (r < BM) ? (At + (long)(row0 + r) * lda + qs_[j] * 4)
                               : (Bt + (long)(col0 + r - BM) * ldb + qs_[j] * 4);
        }

        float acc[MT][NT][4];
        #pragma unroll
        for (int i = 0; i < MT; i++)
            #pragma unroll
            for (int j = 0; j < NT; j++)
                #pragma unroll
                for (int q = 0; q < 4; q++) acc[i][j][q] = 0.f;

        const int nch = K / BK;

        // prologue: LDG chunk 0 into registers
        float4 v[6];
        #pragma unroll
        for (int j = 0; j < 6; j++) v[j] = *(const float4*)(gptr[j]);

        for (int c = 0; c < nch; c++) {
            // pack + STS chunk c
            float* sbuf = sm + (c & 1) * STGW;
            #pragma unroll
            for (int j = 0; j < 6; j++) {
                uint4 pk;
                pk.x = pack_bf16(v[j].x, v[j].y);
                pk.y = pack_bf16(v[j].z, v[j].w);
                pk.z = pack_bf16(resid(v[j].x), resid(v[j].y));
                pk.w = pack_bf16(resid(v[j].z), resid(v[j].w));
                *(uint4*)(sbuf + soff[j]) = pk;
            }
            // prefetch chunk c+1 into registers (overlaps compute below)
            if (c + 1 < nch) {
                const int kk = (c + 1) * BK;
                #pragma unroll
                for (int j = 0; j < 6; j++) v[j] = *(const float4*)(gptr[j] + kk);
            }
            __syncthreads();

            const float* Asm = sm + (c & 1) * STGW;
            const float* Bsm = Asm + BM * RSW;

            #pragma unroll
            for (int ks = 0; ks < 2; ks++) {
                const int qoff = (ks * 4 + tg) * 4;
                uint4 a0[MT], a1[MT];
                #pragma unroll
                for (int mt = 0; mt < MT; mt++) {
                    a0[mt] = *(const uint4*)(Asm + (ar + mt * 16) * RSW + qoff);
                    a1[mt] = *(const uint4*)(Asm + (ar + mt * 16 + 8) * RSW + qoff);
                }
                uint4 bv[NT];
                #pragma unroll
                for (int nt = 0; nt < NT; nt++)
                    bv[nt] = *(const uint4*)(Bsm + (br + nt * 8) * RSW + qoff);

                uint32_t Ah[MT][4], Al[MT][4];
                #pragma unroll
                for (int mt = 0; mt < MT; mt++) {
                    Ah[mt][0] = a0[mt].x; Ah[mt][1] = a1[mt].x;
                    Ah[mt][2] = a0[mt].y; Ah[mt][3] = a1[mt].y;
                    Al[mt][0] = a0[mt].z; Al[mt][1] = a1[mt].z;
                    Al[mt][2] = a0[mt].w; Al[mt][3] = a1[mt].w;
                }
                uint32_t Bh[NT][2], Bl[NT][2];
                #pragma unroll
                for (int nt = 0; nt < NT; nt++) {
                    Bh[nt][0] = bv[nt].x; Bh[nt][1] = bv[nt].y;
                    Bl[nt][0] = bv[nt].z; Bl[nt][1] = bv[nt].w;
                }
                // term-major: breaks accumulator dependency chains
                #pragma unroll
                for (int mt = 0; mt < MT; mt++)
                    #pragma unroll
                    for (int nt = 0; nt < NT; nt++)
                        mma_bf16(acc[mt][nt], Ah[mt], Bh[nt]);
                #pragma unroll
                for (int mt = 0; mt < MT; mt++)
                    #pragma unroll
                    for (int nt = 0; nt < NT; nt++)
                        mma_bf16(acc[mt][nt], Ah[mt], Bl[nt]);
                #pragma unroll
                for (int mt = 0; mt < MT; mt++)
                    #pragma unroll
                    for (int nt = 0; nt < NT; nt++)
                        mma_bf16(acc[mt][nt], Al[mt], Bh[nt]);
            }
            __syncthreads();
        }

        // epilogue
        const int rbase = row0 + wm * 32 + g;
        const int cbase = col0 + wn * 32 + tg * 2;
        #pragma unroll
        for (int mt = 0; mt < MT; mt++) {
            #pragma unroll
            for (int half = 0; half < 2; half++) {
                const long gm = rbase + mt * 16 + half * 8;
                float* crow = Ct + gm * ldc;
                #pragma unroll
                for (int nt = 0; nt < NT; nt++) {
                    const int gn = cbase + nt * 8;
                    float v0 = acc[mt][nt][half * 2 + 0] * alpha;
                    float v1 = acc[mt][nt][half * 2 + 1] * alpha;
                    if (EXP_)  { v0 = __expf(v0); v1 = __expf(v1); }
                    if (BIAS_) { v0 += bias[gn]; v1 += bias[gn + 1]; }
                    if (RELU_) { v0 = fmaxf(v0, 0.f); v1 = fmaxf(v1, 0.f); }
                    float2 o; o.x = v0; o.y = v1;
                    *(float2*)(crow + gn) = o;
                }
            }
        }
    }
}

// ---------------- tiled transpose: out[z][c][r] = in[z][r][c] (* scale[z][r]) -----
template<bool SC>
__global__ void transpose_k(const float* __restrict__ in, float* __restrict__ out,
                            const float* __restrict__ scale,
                            int R, int C, int ldin, int ldout,
                            long inS1, long inS2, int zdiv)
{
    __shared__ float tile[32][33];
    const int z = blockIdx.z;
    in  += (long)(z / zdiv) * inS1 + (long)(z % zdiv) * inS2;
    out += (long)z * (long)C * ldout;
    if (SC) scale += (long)z * R;
    const int c0 = blockIdx.x * 32, r0 = blockIdx.y * 32;
    const int tx = threadIdx.x, ty = threadIdx.y;
    #pragma unroll
    for (int i = ty; i < 32; i += 8) {
        float v = in[(long)(r0 + i) * ldin + c0 + tx];
        if (SC) v *= scale[r0 + i];
        tile[i][tx] = v;
    }
    __syncthreads();
    #pragma unroll
    for (int i = ty; i < 32; i += 8)
        out[(long)(c0 + i) * ldout + r0 + tx] = tile[tx][i];
}

// -------- deterministic per-column (query-axis) softmax denominator --------------
__global__ void colsum_inv(const float* __restrict__ S, float* __restrict__ dinv) {
    const int z = blockIdx.y;
    const int s = blockIdx.x * 256 + threadIdx.x;
    const float* p = S + (long)z * 1048576 + s;
    float acc = 0.f;
    #pragma unroll 8
    for (int t = 0; t < 1024; t++) acc += p[(long)t * 1024];
    dinv[z * 1024 + s] = 1.f / acc;
}

// ---------------- reductions + sub_norm -------------------------------------------
__device__ __forceinline__ float blockReduceSum(float v) {
    __shared__ float sh[32];
    __syncthreads();
    int lane = threadIdx.x & 31, wid = threadIdx.x >> 5;
    #pragma unroll
    for (int o = 16; o; o >>= 1) v += __shfl_xor_sync(0xffffffffu, v, o);
    if (lane == 0) sh[wid] = v;
    __syncthreads();
    if (wid == 0) {
        v = (threadIdx.x < (blockDim.x >> 5)) ? sh[lane] : 0.f;
        #pragma unroll
        for (int o = 16; o; o >>= 1) v += __shfl_xor_sync(0xffffffffu, v, o);
        if (lane == 0) sh[0] = v;
    }
    __syncthreads();
    return sh[0];
}

__global__ void add_subnorm(const float* __restrict__ A, const float* __restrict__ R,
                            float* __restrict__ O) {
    long base = (long)blockIdx.x * 1024;
    int t = threadIdx.x;
    float v[4];
    float s = 0.f;
    #pragma unroll
    for (int j = 0; j < 4; j++) { v[j] = A[base + t + j * 256] + R[base + t + j * 256]; s += v[j]; }
    s = blockReduceSum(s);
    float mean = s * (1.f / 1024.f);
    float q = 0.f;
    #pragma unroll
    for (int j = 0; j < 4; j++) { float d = v[j] - mean; q += d * d; }
    q = blockReduceSum(q);
    float sd = sqrtf(q * (1.f / 1023.f));
    #pragma unroll
    for (int j = 0; j < 4; j++) O[base + t + j * 256] = v[j] - mean - sd;
}

// ---------------- host --------------------------------------------------------------
static const int SMB   = 2 * (128 + 64) * 48 * 4;  // 73,728 B -> 2 CTAs/SM
static const int PGRID = 304;                      // 152 SMs x 2 CTAs

extern "C" void kernel_launch(void* const* d_in, const int* in_sizes, int n_in,
                              void* d_out, int out_size) {
    const float* x    = (const float*)d_in[0];
    const float* y    = (const float*)d_in[1];
    const float* Wq1  = (const float*)d_in[2];
    const float* Wk1  = (const float*)d_in[3];
    const float* Wv1  = (const float*)d_in[4];
    const float* Wo1  = (const float*)d_in[5];
    const float* Wq2  = (const float*)d_in[6];
    const float* Wk2  = (const float*)d_in[7];
    const float* Wv2  = (const float*)d_in[8];
    const float* Wo2  = (const float*)d_in[9];
    const float* W_in = (const float*)d_in[10];
    const float* b_in = (const float*)d_in[11];
    const float* W_out= (const float*)d_in[12];
    const float* b_out= (const float*)d_in[13];
    float* out = (float*)d_out;

    float *Wt0, *Wt1, *Wt2, *WoT, *Q, *K, *V, *Vt, *S, *dinv, *P, *M, *o1, *o2, *hid, *ff;
    cudaGetSymbolAddress((void**)&Wt0, g_Wt0);
    cudaGetSymbolAddress((void**)&Wt1, g_Wt1);
    cudaGetSymbolAddress((void**)&Wt2, g_Wt2);
    cudaGetSymbolAddress((void**)&WoT, g_WoT);
    cudaGetSymbolAddress((void**)&Q,   g_Q);
    cudaGetSymbolAddress((void**)&K,   g_K);
    cudaGetSymbolAddress((void**)&V,   g_V);
    cudaGetSymbolAddress((void**)&Vt,  g_Vt);
    cudaGetSymbolAddress((void**)&S,   g_S);
    cudaGetSymbolAddress((void**)&dinv,g_dinv);
    cudaGetSymbolAddress((void**)&P,   g_P);
    cudaGetSymbolAddress((void**)&M,   g_M);
    cudaGetSymbolAddress((void**)&o1,  g_o1);
    cudaGetSymbolAddress((void**)&o2,  g_o2);
    cudaGetSymbolAddress((void**)&hid, g_hid);
    cudaGetSymbolAddress((void**)&ff,  g_ff);

    cudaFuncSetAttribute(mma_gemm<false,false,false>, cudaFuncAttributeMaxDynamicSharedMemorySize, SMB);
    cudaFuncSetAttribute(mma_gemm<false,false,true >, cudaFuncAttributeMaxDynamicSharedMemorySize, SMB);
    cudaFuncSetAttribute(mma_gemm<true ,true ,false>, cudaFuncAttributeMaxDynamicSharedMemorySize, SMB);
    cudaFuncSetAttribute(mma_gemm<true ,false,false>, cudaFuncAttributeMaxDynamicSharedMemorySize, SMB);

    dim3 blkT(32, 8);
    const long Z0 = 0;

    auto glaunch = [&](int gx, int gy, int gz) {
        int nt = gx * gy * gz;
        return dim3((unsigned)(nt < PGRID ? nt : PGRID), 1, 1);
    };

    auto run_mha = [&](const float* qsrc, const float* kvsrc,
                       const float* Wq, const float* Wk, const float* Wv, const float* Wo,
                       const float* resid_, float* obuf) {
        // repack per-head weights (H,D,dk) -> [(h,k), d]
        dim3 gw(2, 32, HH);
        transpose_k<false><<<gw, blkT>>>(Wq, Wt0, nullptr, 1024, 64, 64, 1024, 65536, 0, 1);
        transpose_k<false><<<gw, blkT>>>(Wk, Wt1, nullptr, 1024, 64, 64, 1024, 65536, 0, 1);
        transpose_k<false><<<gw, blkT>>>(Wv, Wt2, nullptr, 1024, 64, 64, 1024, 65536, 0, 1);

        // projections: (4096,1024) x (1024,1024)^T   tiles: 16 x 32
        mma_gemm<false,false,false><<<glaunch(16,32,1), 256, SMB>>>(
            qsrc, Wt0, nullptr, Q, 1024, 1024, 1024, 1024,
            Z0,Z0,Z0,Z0,Z0,Z0, 1, 1.f, 16, 32, 512);
        mma_gemm<false,false,false><<<glaunch(16,32,1), 256, SMB>>>(
            kvsrc, Wt1, nullptr, K, 1024, 1024, 1024, 1024,
            Z0,Z0,Z0,Z0,Z0,Z0, 1, 1.f, 16, 32, 512);
        mma_gemm<false,false,false><<<glaunch(16,32,1), 256, SMB>>>(
            kvsrc, Wt2, nullptr, V, 1024, 1024, 1024, 1024,
            Z0,Z0,Z0,Z0,Z0,Z0, 1, 1.f, 16, 32, 512);

        // scores: S[(b,h), t, s] = exp( Q.K^T / 8 )   tiles: 16 x 8 x 64
        mma_gemm<false,false,true><<<glaunch(16,8,64), 256, SMB>>>(
            Q, K, nullptr, S, 64, 1024, 1024, 1024,
            1048576, 64, 1048576, 64, 16777216, 1048576, HH, 0.125f, 16, 8, 8192);

        // softmax denominator over query axis t (deterministic column sums)
        colsum_inv<<<dim3(4, BB * HH), 256>>>(S, dinv);

        // V transpose + fold dinv: Vt[(b,h), v, s] = V[b, s, (h,v)] * dinv[(b,h), s]
        dim3 gv(2, 32, BB * HH);
        transpose_k<true><<<gv, blkT>>>(V, Vt, dinv, 1024, 64, 1024, 1024, 1048576, 64, HH);

        // partial: P[b, t, (h,v)] = sum_s expS[t,s] * Vt'[v,s]   tiles: 1 x 8 x 64
        mma_gemm<false,false,false><<<glaunch(1,8,64), 256, SMB>>>(
            S, Vt, nullptr, P, 1024, 1024, 1024, 1024,
            16777216, 1048576, 1048576, 65536, 1048576, 64, HH, 1.f, 1, 8, 512);

        // output projection
        dim3 gwo(32, 32, 1);
        transpose_k<false><<<gwo, blkT>>>(Wo, WoT, nullptr, 1024, 1024, 1024, 1024, Z0, Z0, 1);
        mma_gemm<false,false,false><<<glaunch(16,32,1), 256, SMB>>>(
            P, WoT, nullptr, M, 1024, 1024, 1024, 1024,
            Z0,Z0,Z0,Z0,Z0,Z0, 1, 1.f, 16, 32, 512);

        add_subnorm<<<BB * TT, 256>>>(M, resid_, obuf);
    };

    // out1 = sub_norm(mha(y,y,y) + y)
    run_mha(y, y, Wq1, Wk1, Wv1, Wo1, y, o1);
    // out2 = sub_norm(mha(y,x,x) + out1)
    run_mha(y, x, Wq2, Wk2, Wv2, Wo2, o1, o2);

    // FFN on y: hid = relu(y @ W_in^T + b_in)   tiles: 64 x 32
    mma_gemm<true,true,false><<<glaunch(64,32,1), 256, SMB>>>(
        y, W_in, b_in, hid, 1024, 1024, 1024, 4096,
        Z0,Z0,Z0,Z0,Z0,Z0, 1, 1.f, 64, 32, 2048);
    // ff = hid @ W_out^T + b_out   tiles: 16 x 32
    mma_gemm<true,false,false><<<glaunch(16,32,1), 256, SMB>>>(
        hid, W_out, b_out, ff, 4096, 4096, 4096, 1024,
        Z0,Z0,Z0,Z0,Z0,Z0, 1, 1.f, 16, 32, 512);

    add_subnorm<<<BB * TT, 256>>>(ff, o2, out);
}

// round 7
// speedup vs baseline: 1.0358x; 1.0358x over previous
#include <cuda_runtime.h>
#include <math.h>
#include <stdint.h>

#define BB 4
#define TT 1024
#define DD 1024
#define HH 16
#define DKV 64
#define FFD 4096

// ---- packed split format: per element pair (2k, 2k+1):
//      word0 = [bf16hi(e0) | bf16hi(e1)], word1 = [bf16lo(e0) | bf16lo(e1)]
//      (same 4B/element as fp32; 16B group = 2 pairs = one k-quad)

// ---------------- scratch (device globals; no allocation allowed) ----------------
__device__ float g_xy [2 * BB * TT * DD];            // packed y, x
__device__ float g_Wt [3 * DD * DD];                 // packed q/k/v weights (transposed)
__device__ float g_WoT[DD * DD];                     // packed Wo^T
__device__ float g_Win[FFD * DD];                    // packed W_in
__device__ float g_Wout[DD * FFD];                   // packed W_out
__device__ float g_QKV[3 * BB * TT * DD];            // packed Q,K,V
__device__ float g_Vt [BB * HH * DKV * TT];          // packed Vt (dinv folded)
__device__ float g_S  [(size_t)BB * HH * TT * TT];   // packed exp-scores (256 MB)
__device__ float g_dinv[BB * HH * TT];
__device__ float g_P  [BB * TT * DD];                // packed
__device__ float g_hid[(size_t)BB * TT * FFD];       // packed (64 MB)
__device__ float g_M  [BB * TT * DD];                // fp32
__device__ float g_o1 [BB * TT * DD];
__device__ float g_o2 [BB * TT * DD];
__device__ float g_ff [BB * TT * DD];

// ---------------- helpers ----------------
__device__ __forceinline__ uint32_t pack_bf16(float a, float b) {
    uint32_t d;
    asm("prmt.b32 %0, %1, %2, 0x7632;" : "=r"(d)
        : "r"(__float_as_uint(a)), "r"(__float_as_uint(b)));
    return d;
}
__device__ __forceinline__ float resid(float v) {
    return v - __uint_as_float(__float_as_uint(v) & 0xffff0000u);
}
__device__ __forceinline__ float bf_lo(uint32_t w) {   // halfword 0 -> float
    return __uint_as_float(w << 16);
}
__device__ __forceinline__ float bf_hi(uint32_t w) {   // halfword 1 -> float
    return __uint_as_float(w & 0xffff0000u);
}
__device__ __forceinline__ void mma_bf16(float* c, const uint32_t* a, const uint32_t* b) {
    asm volatile(
        "mma.sync.aligned.m16n8k16.row.col.f32.bf16.bf16.f32 "
        "{%0,%1,%2,%3}, {%4,%5,%6,%7}, {%8,%9}, {%0,%1,%2,%3};"
        : "+f"(c[0]), "+f"(c[1]), "+f"(c[2]), "+f"(c[3])
        : "r"(a[0]), "r"(a[1]), "r"(a[2]), "r"(a[3]), "r"(b[0]), "r"(b[1]));
}

// ---------------- bf16x3 mma GEMM on packed operands -------------------------------
// C[M,N] = alpha * A[M,K] @ B[N,K]^T ; A,B packed-split (addresses in fp32 elements).
// Inner loop: cp.async 16B groups -> LDS.128 -> HMMA. Zero split ALU.
template<bool BIAS_, bool RELU_, bool EXP_, bool PACK_>
__global__ __launch_bounds__(256, 3)
void mma_gemm(const float* __restrict__ A, const float* __restrict__ B,
              const float* __restrict__ bias, float* __restrict__ C,
              int K, int lda, int ldb, int ldc,
              long sA1, long sA2, long sB1, long sB2, long sC1, long sC2,
              int zdiv, float alpha, int gx, int gy, int ntiles)
{
    constexpr int BM = 128, BN = 64, BK = 32;
    constexpr int NT = 4, MT = 2;
    constexpr int RSW = 48;                 // words per smem row (32 data + 16 pad)
    constexpr int STGW = (BM + BN) * RSW;   // 9216 words / stage
    constexpr int NLD = (BM + BN) * 8;      // 16B groups per stage

    extern __shared__ float sm[];
    uint32_t smb;
    asm("{ .reg .u64 t; cvta.to.shared.u64 t, %1; cvt.u32.u64 %0, t; }" : "=r"(smb) : "l"(sm));

    const int tid  = threadIdx.x;
    const int lane = tid & 31;
    const int wid  = tid >> 5;
    const int wm   = wid >> 1;
    const int wn   = wid & 1;
    const int g    = lane >> 2;
    const int tg   = lane & 3;

    const int ar = wm * 32 + g;
    const int br = wn * 32 + g;

    for (int tile = blockIdx.x; tile < ntiles; tile += gridDim.x) {
        const int z   = tile / (gx * gy);
        const int rem = tile % (gx * gy);
        const int row0 = (rem / gx) * BM;
        const int col0 = (rem % gx) * BN;
        const int z1 = z / zdiv, z2 = z % zdiv;
        const float* At = A + z1 * sA1 + z2 * sA2;
        const float* Bt = B + z1 * sB1 + z2 * sB2;
        float*       Ct = C + z1 * sC1 + z2 * sC2;

        float acc[MT][NT][4];
        #pragma unroll
        for (int i = 0; i < MT; i++)
            #pragma unroll
            for (int j = 0; j < NT; j++)
                #pragma unroll
                for (int q = 0; q < 4; q++) acc[i][j][q] = 0.f;

        const int nch = K / BK;

        auto copy_stage = [&](int s, int c) {
            const int kk = c * BK;
            #pragma unroll
            for (int i = tid; i < NLD; i += 256) {
                const bool isA = (i < BM * 8);
                const int j = isA ? i : (i - BM * 8);
                const int r = j >> 3, q = j & 7;
                const float* gp = isA ? (At + (long)(row0 + r) * lda + kk + q * 4)
                                      : (Bt + (long)(col0 + r) * ldb + kk + q * 4);
                uint32_t dst = smb + 4u * (uint32_t)(s * STGW + (isA ? 0 : BM * RSW) + r * RSW + q * 4);
                asm volatile("cp.async.cg.shared.global [%0], [%1], 16;" :: "r"(dst), "l"(gp));
            }
        };

        copy_stage(0, 0);
        asm volatile("cp.async.commit_group;" ::: "memory");

        for (int c = 0; c < nch; c++) {
            if (c + 1 < nch) copy_stage((c + 1) & 1, c + 1);
            asm volatile("cp.async.commit_group;" ::: "memory");
            asm volatile("cp.async.wait_group 1;" ::: "memory");
            __syncthreads();

            const float* Asm = sm + (c & 1) * STGW;
            const float* Bsm = Asm + BM * RSW;

            #pragma unroll
            for (int ks = 0; ks < 2; ks++) {
                const int qoff = (ks * 4 + tg) * 4;
                // group uint4 = (hi01, lo01, hi23, lo23)
                uint4 a0[MT], a1[MT], bv[NT];
                #pragma unroll
                for (int mt = 0; mt < MT; mt++) {
                    a0[mt] = *(const uint4*)(Asm + (ar + mt * 16) * RSW + qoff);
                    a1[mt] = *(const uint4*)(Asm + (ar + mt * 16 + 8) * RSW + qoff);
                }
                #pragma unroll
                for (int nt = 0; nt < NT; nt++)
                    bv[nt] = *(const uint4*)(Bsm + (br + nt * 8) * RSW + qoff);

                uint32_t Ah[MT][4], Al[MT][4], Bh[NT][2], Bl[NT][2];
                #pragma unroll
                for (int mt = 0; mt < MT; mt++) {
                    Ah[mt][0] = a0[mt].x; Ah[mt][1] = a1[mt].x;
                    Ah[mt][2] = a0[mt].z; Ah[mt][3] = a1[mt].z;
                    Al[mt][0] = a0[mt].y; Al[mt][1] = a1[mt].y;
                    Al[mt][2] = a0[mt].w; Al[mt][3] = a1[mt].w;
                }
                #pragma unroll
                for (int nt = 0; nt < NT; nt++) {
                    Bh[nt][0] = bv[nt].x; Bh[nt][1] = bv[nt].z;
                    Bl[nt][0] = bv[nt].y; Bl[nt][1] = bv[nt].w;
                }
                #pragma unroll
                for (int mt = 0; mt < MT; mt++)
                    #pragma unroll
                    for (int nt = 0; nt < NT; nt++)
                        mma_bf16(acc[mt][nt], Ah[mt], Bh[nt]);
                #pragma unroll
                for (int mt = 0; mt < MT; mt++)
                    #pragma unroll
                    for (int nt = 0; nt < NT; nt++)
                        mma_bf16(acc[mt][nt], Ah[mt], Bl[nt]);
                #pragma unroll
                for (int mt = 0; mt < MT; mt++)
                    #pragma unroll
                    for (int nt = 0; nt < NT; nt++)
                        mma_bf16(acc[mt][nt], Al[mt], Bh[nt]);
            }
            __syncthreads();
        }

        // epilogue: thread owns column pairs -> can emit packed pairs directly
        const int rbase = row0 + wm * 32 + g;
        const int cbase = col0 + wn * 32 + tg * 2;
        #pragma unroll
        for (int mt = 0; mt < MT; mt++) {
            #pragma unroll
            for (int half = 0; half < 2; half++) {
                const long gm = rbase + mt * 16 + half * 8;
                float* crow = Ct + gm * ldc;
                #pragma unroll
                for (int nt = 0; nt < NT; nt++) {
                    const int gn = cbase + nt * 8;
                    float v0 = acc[mt][nt][half * 2 + 0] * alpha;
                    float v1 = acc[mt][nt][half * 2 + 1] * alpha;
                    if (EXP_)  { v0 = __expf(v0); v1 = __expf(v1); }
                    if (BIAS_) { v0 += bias[gn]; v1 += bias[gn + 1]; }
                    if (RELU_) { v0 = fmaxf(v0, 0.f); v1 = fmaxf(v1, 0.f); }
                    if (PACK_) {
                        uint2 pk;
                        pk.x = pack_bf16(v0, v1);
                        pk.y = pack_bf16(resid(v0), resid(v1));
                        *(uint2*)(crow + gn) = pk;
                    } else {
                        float2 o; o.x = v0; o.y = v1;
                        *(float2*)(crow + gn) = o;
                    }
                }
            }
        }
    }
}

// -------- split pass: fp32 -> packed (pairs), N even --------------------------------
__global__ void split_pairs(const float* __restrict__ in, float* __restrict__ out, int npairs) {
    int i = blockIdx.x * 256 + threadIdx.x;
    if (i >= npairs) return;
    float2 v = *(const float2*)(in + 2 * i);
    uint2 pk;
    pk.x = pack_bf16(v.x, v.y);
    pk.y = pack_bf16(resid(v.x), resid(v.y));
    *(uint2*)(out + 2 * i) = pk;
}

// -------- transpose: out[z][c][r] = in[z][r][c] (*scale[z][r]), packed output -------
// PIN: input is packed-split (reconstruct hi+lo); SC: multiply scale[input row]
template<bool SC, bool PIN>
__global__ void transpose_pk(const float* __restrict__ in, float* __restrict__ out,
                             const float* __restrict__ scale,
                             int R, int ldin, int ldout,
                             long inS1, long inS2, int zdiv)
{
    __shared__ float tile[32][33];
    const int z = blockIdx.z;
    in  += (long)(z / zdiv) * inS1 + (long)(z % zdiv) * inS2;
    out += (long)z * 0;  // caller folds z into out via outZ stride below
    const long outz = (long)z * (long)gridDim.x * 32 * ldout;   // C = gridDim.x*32
    const int c0 = blockIdx.x * 32, r0 = blockIdx.y * 32;
    const int tx = threadIdx.x, ty = threadIdx.y;
    #pragma unroll
    for (int i = ty; i < 32; i += 8) {
        float v;
        if (PIN) {
            const uint32_t* ip = (const uint32_t*)(in + (long)(r0 + i) * ldin + ((c0 + tx) & ~1));
            uint32_t w0 = ip[0], w1 = ip[1];
            if ((tx & 1) == 0) v = bf_lo(w0) + bf_lo(w1);
            else               v = bf_hi(w0) + bf_hi(w1);
        } else {
            v = in[(long)(r0 + i) * ldin + c0 + tx];
        }
        if (SC) v *= scale[(long)z * R + r0 + i];
        tile[i][tx] = v;
    }
    __syncthreads();
    // packed write: 512 pairs, 256 threads -> 2 each
    const int idx = ty * 32 + tx;
    const int p  = idx & 15;          // pair column (r-dim)
    const int cr = idx >> 4;          // 0..15
    #pragma unroll
    for (int rr0 = 0; rr0 < 2; rr0++) {
        const int rr = cr + rr0 * 16;
        float v0 = tile[2 * p][rr];
        float v1 = tile[2 * p + 1][rr];
        uint2 pk;
        pk.x = pack_bf16(v0, v1);
        pk.y = pack_bf16(resid(v0), resid(v1));
        *(uint2*)(out + outz + (long)(c0 + rr) * ldout + r0 + 2 * p) = pk;
    }
}

// -------- deterministic per-column softmax denominator (packed S) -------------------
__global__ void colsum_inv(const float* __restrict__ S, float* __restrict__ dinv) {
    const int z = blockIdx.y;
    const int sp = blockIdx.x * 256 + threadIdx.x;    // pair index 0..511
    const uint32_t* p = (const uint32_t*)(S + (long)z * 1048576 + 2 * sp);
    float a0 = 0.f, a1 = 0.f;
    #pragma unroll 4
    for (int t = 0; t < 1024; t++) {
        uint32_t w0 = p[(long)t * 1024];
        uint32_t w1 = p[(long)t * 1024 + 1];
        a0 += bf_lo(w0) + bf_lo(w1);
        a1 += bf_hi(w0) + bf_hi(w1);
    }
    dinv[z * 1024 + 2 * sp]     = 1.f / a0;
    dinv[z * 1024 + 2 * sp + 1] = 1.f / a1;
}

// ---------------- reductions + sub_norm ---------------------------------------------
__device__ __forceinline__ float blockReduceSum(float v) {
    __shared__ float sh[32];
    __syncthreads();
    int lane = threadIdx.x & 31, wid = threadIdx.x >> 5;
    #pragma unroll
    for (int o = 16; o; o >>= 1) v += __shfl_xor_sync(0xffffffffu, v, o);
    if (lane == 0) sh[wid] = v;
    __syncthreads();
    if (wid == 0) {
        v = (threadIdx.x < (blockDim.x >> 5)) ? sh[lane] : 0.f;
        #pragma unroll
        for (int o = 16; o; o >>= 1) v += __shfl_xor_sync(0xffffffffu, v, o);
        if (lane == 0) sh[0] = v;
    }
    __syncthreads();
    return sh[0];
}

__global__ void add_subnorm(const float* __restrict__ A, const float* __restrict__ R,
                            float* __restrict__ O) {
    long base = (long)blockIdx.x * 1024;
    int t = threadIdx.x;
    float v[4];
    float s = 0.f;
    #pragma unroll
    for (int j = 0; j < 4; j++) { v[j] = A[base + t + j * 256] + R[base + t + j * 256]; s += v[j]; }
    s = blockReduceSum(s);
    float mean = s * (1.f / 1024.f);
    float q = 0.f;
    #pragma unroll
    for (int j = 0; j < 4; j++) { float d = v[j] - mean; q += d * d; }
    q = blockReduceSum(q);
    float sd = sqrtf(q * (1.f / 1023.f));
    #pragma unroll
    for (int j = 0; j < 4; j++) O[base + t + j * 256] = v[j] - mean - sd;
}

// ---------------- host ----------------------------------------------------------------
static const int SMB   = 2 * (128 + 64) * 48 * 4;  // 73,728 B -> 3 CTAs/SM
static const int PGRID = 456;

extern "C" void kernel_launch(void* const* d_in, const int* in_sizes, int n_in,
                              void* d_out, int out_size) {
    const float* x    = (const float*)d_in[0];
    const float* y    = (const float*)d_in[1];
    const float* Wq1  = (const float*)d_in[2];
    const float* Wk1  = (const float*)d_in[3];
    const float* Wv1  = (const float*)d_in[4];
    const float* Wo1  = (const float*)d_in[5];
    const float* Wq2  = (const float*)d_in[6];
    const float* Wk2  = (const float*)d_in[7];
    const float* Wv2  = (const float*)d_in[8];
    const float* Wo2  = (const float*)d_in[9];
    const float* W_in = (const float*)d_in[10];
    const float* b_in = (const float*)d_in[11];
    const float* W_out= (const float*)d_in[12];
    const float* b_out= (const float*)d_in[13];
    float* out = (float*)d_out;

    float *xy, *Wt, *WoT, *Win, *Wout, *QKV, *Vt, *S, *dinv, *P, *hid, *M, *o1, *o2, *ff;
    cudaGetSymbolAddress((void**)&xy,  g_xy);
    cudaGetSymbolAddress((void**)&Wt,  g_Wt);
    cudaGetSymbolAddress((void**)&WoT, g_WoT);
    cudaGetSymbolAddress((void**)&Win, g_Win);
    cudaGetSymbolAddress((void**)&Wout,g_Wout);
    cudaGetSymbolAddress((void**)&QKV, g_QKV);
    cudaGetSymbolAddress((void**)&Vt,  g_Vt);
    cudaGetSymbolAddress((void**)&S,   g_S);
    cudaGetSymbolAddress((void**)&dinv,g_dinv);
    cudaGetSymbolAddress((void**)&P,   g_P);
    cudaGetSymbolAddress((void**)&hid, g_hid);
    cudaGetSymbolAddress((void**)&M,   g_M);
    cudaGetSymbolAddress((void**)&o1,  g_o1);
    cudaGetSymbolAddress((void**)&o2,  g_o2);
    cudaGetSymbolAddress((void**)&ff,  g_ff);

    cudaFuncSetAttribute(mma_gemm<false,false,false,true >, cudaFuncAttributeMaxDynamicSharedMemorySize, SMB);
    cudaFuncSetAttribute(mma_gemm<false,false,true ,true >, cudaFuncAttributeMaxDynamicSharedMemorySize, SMB);
    cudaFuncSetAttribute(mma_gemm<false,false,false,false>, cudaFuncAttributeMaxDynamicSharedMemorySize, SMB);
    cudaFuncSetAttribute(mma_gemm<true ,true ,false,true >, cudaFuncAttributeMaxDynamicSharedMemorySize, SMB);
    cudaFuncSetAttribute(mma_gemm<true ,false,false,false>, cudaFuncAttributeMaxDynamicSharedMemorySize, SMB);

    const long Z0 = 0;
    const long XL = (long)BB * TT * DD;     // 4,194,304
    const long WL = (long)DD * DD;          // 1,048,576
    const long CL = (long)BB * TT * DD;     // per-QKV-slice
    dim3 blkT(32, 8);

    auto glaunch = [&](int nt) { return dim3((unsigned)(nt < PGRID ? nt : PGRID), 1, 1); };

    // ---- upfront splits: y -> xy[0], x -> xy[1], W_in, W_out
    split_pairs<<<(int)(XL/2 + 255)/256, 256>>>(y, xy, (int)(XL/2));
    split_pairs<<<(int)(XL/2 + 255)/256, 256>>>(x, xy + XL, (int)(XL/2));
    split_pairs<<<(int)(WL*4/2 + 255)/256, 256>>>(W_in,  Win,  (int)(WL*4/2));
    split_pairs<<<(int)(WL*4/2 + 255)/256, 256>>>(W_out, Wout, (int)(WL*4/2));

    auto run_mha = [&](long aS, const float* Wq, const float* Wk, const float* Wv,
                       const float* Wo, const float* resid_, float* obuf) {
        // repack per-head weights (H,D,dk) -> packed [(h,k), d], 3 weights into g_Wt
        dim3 gw(2, 32, HH);
        transpose_pk<false,false><<<gw, blkT>>>(Wq, Wt,          nullptr, 1024, 64, 1024, 65536, 0, 1);
        transpose_pk<false,false><<<gw, blkT>>>(Wk, Wt + WL,     nullptr, 1024, 64, 1024, 65536, 0, 1);
        transpose_pk<false,false><<<gw, blkT>>>(Wv, Wt + 2 * WL, nullptr, 1024, 64, 1024, 65536, 0, 1);

        // merged QKV projections: z=0:Q(A off 0), z=1:K(A off aS), z=2:V(A off aS)
        // zdiv=2: offsets z->(z1,z2): 0,sA2,sA1 ; B: 0,WL,2WL ; C: 0,CL,2CL
        mma_gemm<false,false,false,true><<<glaunch(1536), 256, SMB>>>(
            xy, Wt, nullptr, QKV, 1024, 1024, 1024, 1024,
            aS, aS, 2*WL, WL, 2*CL, CL, 2, 1.f, 16, 32, 1536);

        // scores: S[(b,h), t, s] = exp( Q.K^T / 8 )  (packed out)
        mma_gemm<false,false,true,true><<<glaunch(8192), 256, SMB>>>(
            QKV, QKV + CL, nullptr, S, 64, 1024, 1024, 1024,
            1048576, 64, 1048576, 64, 16777216, 1048576, HH, 0.125f, 16, 8, 8192);

        // softmax denominator over query axis t
        colsum_inv<<<dim3(2, BB * HH), 256>>>(S, dinv);

        // Vt: packed V -> fp32 -> *dinv -> packed [bh][v][s]
        dim3 gv(2, 32, BB * HH);
        transpose_pk<true,true><<<gv, blkT>>>(QKV + 2 * CL, Vt, dinv, 1024, 1024, 1024,
                                              1048576, 64, HH);

        // partial: P[b, t, (h,v)] = sum_s S[t,s] * Vt[v,s]  (packed out)
        mma_gemm<false,false,false,true><<<glaunch(512), 256, SMB>>>(
            S, Vt, nullptr, P, 1024, 1024, 1024, 1024,
            16777216, 1048576, 1048576, 65536, 1048576, 64, HH, 1.f, 1, 8, 512);

        // output projection (fp32 out)
        dim3 gwo(32, 32, 1);
        transpose_pk<false,false><<<gwo, blkT>>>(Wo, WoT, nullptr, 1024, 1024, 1024, Z0, Z0, 1);
        mma_gemm<false,false,false,false><<<glaunch(512), 256, SMB>>>(
            P, WoT, nullptr, M, 1024, 1024, 1024, 1024,
            Z0,Z0,Z0,Z0,Z0,Z0, 1, 1.f, 16, 32, 512);

        add_subnorm<<<BB * TT, 256>>>(M, resid_, obuf);
    };

    // out1 = sub_norm(mha(y,y,y) + y):   A offsets all 0 (y)
    run_mha(0,  Wq1, Wk1, Wv1, Wo1, y, o1);
    // out2 = sub_norm(mha(y,x,x) + out1): Q from y (off 0), K/V from x (off XL)
    run_mha(XL, Wq2, Wk2, Wv2, Wo2, o1, o2);

    // FFN on y: hid = relu(y @ W_in^T + b_in)  (packed out)
    mma_gemm<true,true,false,true><<<glaunch(2048), 256, SMB>>>(
        xy, Win, b_in, hid, 1024, 1024, 1024, 4096,
        Z0,Z0,Z0,Z0,Z0,Z0, 1, 1.f, 64, 32, 2048);
    // ff = hid @ W_out^T + b_out  (fp32 out)
    mma_gemm<true,false,false,false><<<glaunch(512), 256, SMB>>>(
        hid, Wout, b_out, ff, 4096, 4096, 4096, 1024,
        Z0,Z0,Z0,Z0,Z0,Z0, 1, 1.f, 16, 32, 512);

    add_subnorm<<<BB * TT, 256>>>(ff, o2, out);
}